// round 2
// baseline (speedup 1.0000x reference)
#include <cuda_runtime.h>

// ---------------------------------------------------------------------------
// VQ-VAE forward, fp32, arithmetic-order matched to XLA:CPU (Eigen) reference.
// Encoder convs: single sequential FMA chain per output over (kh, kw, ic),
// ic innermost (Eigen NHWC im2col + gebp order).
// VQ dist: (zz - fl(2*dot)) + en, zz/en sequential mul+add (no FMA),
// dot sequential FMA over c ascending. argmin: first min wins.
// dec_in = fl(ze + fl(zq - ze)). Decoder: any fp32 order (1e-3 tolerance).
// ---------------------------------------------------------------------------

__device__ float g_h1[64 * 32 * 128 * 128];
__device__ float g_h2[64 * 64 * 64 * 64];
__device__ float g_d1o[64 * 32 * 64 * 64];
__device__ float g_d2o[64 * 64 * 128 * 128];
__device__ float g_en[512];

// ------------------------- e1: 1->32, k4 s2 p1, relu -----------------------
// ic=1, so chain order (kh,kw) is unambiguous. One thread = one ow, 32 oc.
__global__ __launch_bounds__(128) void k_e1(const float* __restrict__ x,
                                            const float* __restrict__ w,
                                            const float* __restrict__ b) {
    __shared__ float s_in[4 * 258];
    __shared__ float s_w[512];
    const int oh = blockIdx.x, n = blockIdx.y, t = threadIdx.x;
    for (int i = t; i < 4 * 258; i += 128) {
        int r = i / 258, c = i % 258;
        int ih = 2 * oh - 1 + r, iw = c - 1;
        s_in[i] = (ih >= 0 && ih < 256 && iw >= 0 && iw < 256)
                      ? x[n * 65536 + ih * 256 + iw] : 0.f;
    }
    for (int i = t; i < 512; i += 128) s_w[i] = w[i];
    __syncthreads();
    float acc[32];
#pragma unroll
    for (int o = 0; o < 32; o++) acc[o] = 0.f;
    const int ow = t;
#pragma unroll
    for (int k = 0; k < 16; k++) {      // k = kh*4+kw ascending (Eigen order)
        float v = s_in[(k >> 2) * 258 + 2 * ow + (k & 3)];
#pragma unroll
        for (int o = 0; o < 32; o++) acc[o] = fmaf(v, s_w[o * 16 + k], acc[o]);
    }
    for (int o = 0; o < 32; o++) {
        float r = __fadd_rn(acc[o], b[o]);
        g_h1[((n * 32 + o) * 128 + oh) * 128 + ow] = r > 0.f ? r : 0.f;
    }
}

// ------------------------- e2: 32->64, k4 s2 p1, relu ----------------------
// Chain order per output: kh, kw outer; ic (0..31) innermost, sequential.
// Block: one (n, oh) row x 32 oc (ocg in blockIdx.z). Dynamic smem.
// Thread: 2 ow (tow, tow+32) x 4 oc.
__global__ __launch_bounds__(256) void k_e2(const float* __restrict__ w,
                                            const float* __restrict__ b) {
    extern __shared__ float sm[];
    float* s_in = sm;            // [ic(32)][r(4)][130] = 16640
    float* s_w  = sm + 16640;    // [ic(32)][ocl(32)][k(16)] = 16384
    const int oh = blockIdx.x, n = blockIdx.y, ocg = blockIdx.z, t = threadIdx.x;
    const int tow = t & 31, g = t >> 5;   // g in [0,8), 4 oc each
    for (int i = t; i < 16640; i += 256) {
        int ic = i / 520, rem = i % 520;
        int r = rem / 130, c = rem % 130;
        int ih = 2 * oh - 1 + r, iw = c - 1;
        s_in[i] = (ih >= 0 && ih < 128 && iw >= 0 && iw < 128)
                      ? g_h1[((n * 32 + ic) * 128 + ih) * 128 + iw] : 0.f;
    }
    for (int i = t; i < 16384; i += 256) {
        int ic = i >> 9, ocl = (i >> 4) & 31, k = i & 15;
        s_w[i] = w[(((ocg * 32 + ocl) * 32 + ic) << 4) + k];
    }
    __syncthreads();
    float acc[4][2];
#pragma unroll
    for (int j = 0; j < 4; j++) { acc[j][0] = 0.f; acc[j][1] = 0.f; }
#pragma unroll
    for (int kh = 0; kh < 4; kh++) {
#pragma unroll
        for (int kw = 0; kw < 4; kw++) {
#pragma unroll 4
            for (int ic = 0; ic < 32; ic++) {
                float v0 = s_in[ic * 520 + kh * 130 + 2 * tow + kw];
                float v1 = s_in[ic * 520 + kh * 130 + 2 * tow + 64 + kw];
#pragma unroll
                for (int j = 0; j < 4; j++) {
                    float wv = s_w[((ic * 32 + g * 4 + j) << 4) + kh * 4 + kw];
                    acc[j][0] = fmaf(v0, wv, acc[j][0]);
                    acc[j][1] = fmaf(v1, wv, acc[j][1]);
                }
            }
        }
    }
    for (int j = 0; j < 4; j++) {
        int oc = ocg * 32 + g * 4 + j;
        float bv = b[oc];
        float r0 = __fadd_rn(acc[j][0], bv);
        float r1 = __fadd_rn(acc[j][1], bv);
        g_h2[((n * 64 + oc) * 64 + oh) * 64 + tow]      = r0 > 0.f ? r0 : 0.f;
        g_h2[((n * 64 + oc) * 64 + oh) * 64 + tow + 32] = r1 > 0.f ? r1 : 0.f;
    }
}

// ------------------------- e3: 64->64, k3 s1 p1, relu ----------------------
// Chain order: kh, kw outer; ic (0..63) innermost, sequential.
__global__ __launch_bounds__(256) void k_e3(const float* __restrict__ w,
                                            const float* __restrict__ b,
                                            float* __restrict__ ze) {
    extern __shared__ float sm[];
    float* s_in = sm;            // [ic(64)][r(3)][66] = 12672
    float* s_w  = sm + 12672;    // [ic(64)][ocl(32)][k(9)] = 18432
    const int oh = blockIdx.x, n = blockIdx.y, ocg = blockIdx.z, t = threadIdx.x;
    const int tow = t & 31, g = t >> 5;
    for (int i = t; i < 12672; i += 256) {
        int ic = i / 198, rem = i % 198;
        int r = rem / 66, c = rem % 66;
        int ih = oh - 1 + r, iw = c - 1;
        s_in[i] = (ih >= 0 && ih < 64 && iw >= 0 && iw < 64)
                      ? g_h2[((n * 64 + ic) * 64 + ih) * 64 + iw] : 0.f;
    }
    for (int i = t; i < 18432; i += 256) {
        int ic = i / 288, rem = i % 288;
        int ocl = rem / 9, k = rem % 9;
        s_w[i] = w[(((ocg * 32 + ocl) * 64 + ic)) * 9 + k];
    }
    __syncthreads();
    float acc[4][2];
#pragma unroll
    for (int j = 0; j < 4; j++) { acc[j][0] = 0.f; acc[j][1] = 0.f; }
#pragma unroll
    for (int kh = 0; kh < 3; kh++) {
#pragma unroll
        for (int kw = 0; kw < 3; kw++) {
#pragma unroll 4
            for (int ic = 0; ic < 64; ic++) {
                float v0 = s_in[ic * 198 + kh * 66 + tow + kw];
                float v1 = s_in[ic * 198 + kh * 66 + tow + 32 + kw];
#pragma unroll
                for (int j = 0; j < 4; j++) {
                    float wv = s_w[(ic * 32 + g * 4 + j) * 9 + kh * 3 + kw];
                    acc[j][0] = fmaf(v0, wv, acc[j][0]);
                    acc[j][1] = fmaf(v1, wv, acc[j][1]);
                }
            }
        }
    }
    for (int j = 0; j < 4; j++) {
        int oc = ocg * 32 + g * 4 + j;
        float bv = b[oc];
        float r0 = __fadd_rn(acc[j][0], bv);
        float r1 = __fadd_rn(acc[j][1], bv);
        ze[((n * 64 + oc) * 64 + oh) * 64 + tow]      = r0 > 0.f ? r0 : 0.f;
        ze[((n * 64 + oc) * 64 + oh) * 64 + tow + 32] = r1 > 0.f ? r1 : 0.f;
    }
}

// ------------------------- codebook norms (sequential mul+add) -------------
__global__ void k_en(const float* __restrict__ emb) {
    int k = blockIdx.x * blockDim.x + threadIdx.x;
    if (k < 512) {
        float s = 0.f;
        for (int c = 0; c < 64; c++) {
            float v = emb[k * 64 + c];
            s = __fadd_rn(s, __fmul_rn(v, v));
        }
        g_en[k] = s;
    }
}

// ------------------------- VQ argmin + gather ------------------------------
__global__ __launch_bounds__(256) void k_vq(const float* __restrict__ ze,
                                            const float* __restrict__ emb,
                                            float* __restrict__ zq) {
    __shared__ float s_z[4096];   // [c(64)][pos(64)]
    __shared__ float s_zz[64];
    __shared__ float s_e[4096];   // [code_local(64)][c(64)]
    __shared__ float s_en[512];
    __shared__ float s_bv[256];
    __shared__ int s_bi[256];
    __shared__ int s_idx[64];
    const int h = blockIdx.x, n = blockIdx.y, t = threadIdx.x;
    const int pos = t & 63, kg = t >> 6;
    for (int i = t; i < 4096; i += 256)
        s_z[i] = ze[(n * 64 + (i >> 6)) * 4096 + h * 64 + (i & 63)];
    for (int i = t; i < 512; i += 256) s_en[i] = g_en[i];
    __syncthreads();
    if (t < 64) {
        float a = 0.f;
        for (int c = 0; c < 64; c++) {
            float v = s_z[c * 64 + t];
            a = __fadd_rn(a, __fmul_rn(v, v));
        }
        s_zz[t] = a;
    }
    float bv = 3.4e38f;
    int bi = 0;
    for (int ch = 0; ch < 8; ch++) {
        __syncthreads();
        for (int i = t; i < 4096; i += 256) s_e[i] = emb[ch * 4096 + i];
        __syncthreads();
        const float zz = s_zz[pos];
        float dot[16];
#pragma unroll
        for (int j = 0; j < 16; j++) dot[j] = 0.f;
        for (int c = 0; c < 64; c++) {   // c ascending (Eigen gemm k order)
            float v = s_z[c * 64 + pos];
#pragma unroll
            for (int j = 0; j < 16; j++)
                dot[j] = fmaf(v, s_e[(kg * 16 + j) * 64 + c], dot[j]);
        }
#pragma unroll
        for (int j = 0; j < 16; j++) {
            int code = ch * 64 + kg * 16 + j;
            float B = __fmul_rn(2.0f, dot[j]);
            float d = __fadd_rn(__fsub_rn(zz, B), s_en[code]);
            if (d < bv) { bv = d; bi = code; }
        }
    }
    s_bv[t] = bv;
    s_bi[t] = bi;
    __syncthreads();
    if (t < 64) {
        for (int q = 1; q < 4; q++) {
            float v2 = s_bv[t + q * 64];
            int i2 = s_bi[t + q * 64];
            if (v2 < bv || (v2 == bv && i2 < bi)) { bv = v2; bi = i2; }
        }
        s_idx[t] = bi;
    }
    __syncthreads();
    for (int i = t; i < 4096; i += 256) {
        int c = i >> 6, wq = i & 63;
        zq[(n * 64 + c) * 4096 + h * 64 + wq] = emb[s_idx[wq] * 64 + c];
    }
}

// --------------- d1: convT 64->32, k3 s1 p1, relu; input = ze+(zq-ze) ------
__global__ __launch_bounds__(256) void k_d1(const float* __restrict__ ze,
                                            const float* __restrict__ zq,
                                            const float* __restrict__ w,
                                            const float* __restrict__ b) {
    __shared__ float s_in[16 * 198];
    __shared__ float s_w[16 * 288];
    const int oh = blockIdx.x, n = blockIdx.y, t = threadIdx.x;
    const int ow = t & 63, g = t >> 6;
    float acc[8];
#pragma unroll
    for (int j = 0; j < 8; j++) acc[j] = 0.f;
    for (int cc = 0; cc < 4; cc++) {
        __syncthreads();
        for (int i = t; i < 3168; i += 256) {
            int ic = i / 198, rem = i % 198;
            int r = rem / 66, c = rem % 66;
            int ih = oh - 1 + r, iw = c - 1;
            float v = 0.f;
            if (ih >= 0 && ih < 64 && iw >= 0 && iw < 64) {
                int off = ((n * 64 + cc * 16 + ic) * 64 + ih) * 64 + iw;
                float a = ze[off], q = zq[off];
                v = __fadd_rn(a, __fsub_rn(q, a));
            }
            s_in[i] = v;
        }
        for (int i = t; i < 4608; i += 256) {
            int ic = i / 288, rem = i % 288;
            int oc = rem / 9, k = rem % 9;
            s_w[i] = w[((cc * 16 + ic) * 32 + oc) * 9 + 8 - k];
        }
        __syncthreads();
        for (int ic = 0; ic < 16; ic++) {
#pragma unroll
            for (int k = 0; k < 9; k++) {
                float v = s_in[ic * 198 + (k / 3) * 66 + ow + (k % 3)];
#pragma unroll
                for (int j = 0; j < 8; j++)
                    acc[j] = fmaf(v, s_w[ic * 288 + (g * 8 + j) * 9 + k], acc[j]);
            }
        }
    }
    for (int j = 0; j < 8; j++) {
        int oc = g * 8 + j;
        float r = __fadd_rn(acc[j], b[oc]);
        g_d1o[((n * 32 + oc) * 64 + oh) * 64 + ow] = r > 0.f ? r : 0.f;
    }
}

// --------------- d2: convT 32->64, k4 s2 p1, relu (parity-decomposed) ------
__global__ __launch_bounds__(512) void k_d2(const float* __restrict__ w,
                                            const float* __restrict__ b) {
    __shared__ float s_in[16 * 132];
    __shared__ float s_w[8192];
    const int oh = blockIdx.x, n = blockIdx.y, t = threadIdx.x;
    const int ow = t & 127, g = t >> 7;
    const int kh_a = 1 - (oh & 1);
    const int ih_a = (oh + 1 - kh_a) >> 1;
    const int ih_b = ih_a - 1;
    const int kw_a = 1 - (ow & 1);
    const int iw_a = (ow + 1 - kw_a) >> 1;
    float acc[16];
#pragma unroll
    for (int j = 0; j < 16; j++) acc[j] = 0.f;
    for (int cc = 0; cc < 2; cc++) {
        __syncthreads();
        for (int i = t; i < 2112; i += 512) {
            int ic = i / 132, rem = i % 132;
            int r = rem / 66, c = rem % 66;
            int ih = (r == 0) ? ih_a : ih_b;
            int iw = c - 1;
            s_in[i] = (ih >= 0 && ih < 64 && iw >= 0 && iw < 64)
                          ? g_d1o[((n * 32 + cc * 16 + ic) * 64 + ih) * 64 + iw] : 0.f;
        }
        for (int i = t; i < 8192; i += 512) {
            int ic = i >> 9, rem = i & 511;
            int oc = rem >> 3, r = (rem >> 2) & 1, kw = rem & 3;
            int kh = kh_a + 2 * r;
            s_w[i] = w[(((cc * 16 + ic) * 64 + oc) << 4) + kh * 4 + kw];
        }
        __syncthreads();
        for (int ic = 0; ic < 16; ic++) {
#pragma unroll
            for (int r = 0; r < 2; r++) {
#pragma unroll
                for (int m = 0; m < 2; m++) {
                    float v = s_in[ic * 132 + r * 66 + iw_a - m + 1];
                    int kw = kw_a + 2 * m;
#pragma unroll
                    for (int j = 0; j < 16; j++)
                        acc[j] = fmaf(v, s_w[(ic << 9) + ((g * 16 + j) << 3) + r * 4 + kw], acc[j]);
                }
            }
        }
    }
    for (int j = 0; j < 16; j++) {
        int oc = g * 16 + j;
        float r = __fadd_rn(acc[j], b[oc]);
        g_d2o[((n * 64 + oc) * 128 + oh) * 128 + ow] = r > 0.f ? r : 0.f;
    }
}

// --------------- d3: convT 64->1, k4 s2 p1 (no relu) -----------------------
__global__ __launch_bounds__(256) void k_d3(const float* __restrict__ w,
                                            const float* __restrict__ bb,
                                            float* __restrict__ xh) {
    __shared__ float s_in[32 * 260];
    __shared__ float s_w[512];
    const int oh = blockIdx.x, n = blockIdx.y, t = threadIdx.x;
    const int ow = t;
    const int kh_a = 1 - (oh & 1);
    const int ih_a = (oh + 1 - kh_a) >> 1;
    const int ih_b = ih_a - 1;
    const int kw_a = 1 - (ow & 1);
    const int iw_a = (ow + 1 - kw_a) >> 1;
    for (int i = t; i < 512; i += 256) {
        int ic = i >> 3, r = (i >> 2) & 1, kw = i & 3;
        int kh = kh_a + 2 * r;
        s_w[i] = w[ic * 16 + kh * 4 + kw];
    }
    float acc = 0.f;
    for (int cc = 0; cc < 2; cc++) {
        __syncthreads();
        for (int i = t; i < 8320; i += 256) {
            int ic = i / 260, rem = i % 260;
            int r = rem / 130, c = rem % 130;
            int ih = (r == 0) ? ih_a : ih_b;
            int iw = c - 1;
            s_in[i] = (ih >= 0 && ih < 128 && iw >= 0 && iw < 128)
                          ? g_d2o[((n * 64 + cc * 32 + ic) * 128 + ih) * 128 + iw] : 0.f;
        }
        __syncthreads();
        for (int ic = 0; ic < 32; ic++) {
#pragma unroll
            for (int r = 0; r < 2; r++) {
#pragma unroll
                for (int m = 0; m < 2; m++) {
                    float v = s_in[ic * 260 + r * 130 + iw_a - m + 1];
                    acc = fmaf(v, s_w[((cc * 32 + ic) << 3) + r * 4 + kw_a + 2 * m], acc);
                }
            }
        }
    }
    xh[n * 65536 + oh * 256 + ow] = __fadd_rn(acc, bb[0]);
}

// ---------------------------------------------------------------------------
extern "C" void kernel_launch(void* const* d_in, const int* in_sizes, int n_in,
                              void* d_out, int out_size) {
    const float* x   = (const float*)d_in[0];
    const float* e1w = (const float*)d_in[1];
    const float* e1b = (const float*)d_in[2];
    const float* e2w = (const float*)d_in[3];
    const float* e2b = (const float*)d_in[4];
    const float* e3w = (const float*)d_in[5];
    const float* e3b = (const float*)d_in[6];
    const float* emb = (const float*)d_in[7];
    const float* d1w = (const float*)d_in[8];
    const float* d1b = (const float*)d_in[9];
    const float* d2w = (const float*)d_in[10];
    const float* d2b = (const float*)d_in[11];
    const float* d3w = (const float*)d_in[12];
    const float* d3b = (const float*)d_in[13];

    float* out = (float*)d_out;
    float* xh = out;
    float* ze = out + 4194304;
    float* zq = out + 4194304 + 16777216;

    static bool attr_done = false;
    if (!attr_done) {
        cudaFuncSetAttribute(k_e2, cudaFuncAttributeMaxDynamicSharedMemorySize, 132096);
        cudaFuncSetAttribute(k_e3, cudaFuncAttributeMaxDynamicSharedMemorySize, 124416);
        attr_done = true;
    }

    k_e1<<<dim3(128, 64), 128>>>(x, e1w, e1b);
    k_e2<<<dim3(64, 64, 2), 256, 132096>>>(e2w, e2b);
    k_e3<<<dim3(64, 64, 2), 256, 124416>>>(e3w, e3b, ze);
    k_en<<<2, 256>>>(emb);
    k_vq<<<dim3(64, 64), 256>>>(ze, emb, zq);
    k_d1<<<dim3(64, 64), 256>>>(ze, zq, d1w, d1b);
    k_d2<<<dim3(128, 64), 512>>>(d2w, d2b);
    k_d3<<<dim3(256, 64), 256>>>(d3w, d3b, xh);
}

// round 3
// speedup vs baseline: 1.0991x; 1.0991x over previous
#include <cuda_runtime.h>

// ---------------------------------------------------------------------------
// VQ-VAE forward, fp32, Eigen-chain-order-exact encoder/VQ, f32x2-packed FMA.
// Each f32x2 lane is an independent sequential fp32 FMA chain (bitwise equal
// to scalar), lanes = two output channels / two codebook codes.
// ---------------------------------------------------------------------------

typedef unsigned long long u64;

__device__ float g_h1[64 * 32 * 128 * 128];
__device__ float g_h2[64 * 64 * 64 * 64];
__device__ float g_d1o[64 * 32 * 64 * 64];
__device__ float g_d2o[64 * 64 * 128 * 128];
__device__ float g_en[512];
__device__ float g_embT[64 * 512];   // [c][code]

__device__ __forceinline__ u64 pk2(float x, float y) {
    u64 r; asm("mov.b64 %0, {%1, %2};" : "=l"(r) : "f"(x), "f"(y)); return r;
}
__device__ __forceinline__ u64 f2fma(u64 a, u64 b, u64 c) {
    u64 d; asm("fma.rn.f32x2 %0, %1, %2, %3;" : "=l"(d) : "l"(a), "l"(b), "l"(c)); return d;
}
__device__ __forceinline__ float2 upk(u64 v) {
    float2 f; asm("mov.b64 {%0, %1}, %2;" : "=f"(f.x), "=f"(f.y) : "l"(v)); return f;
}

// ------------------------- e1: 1->32, k4 s2 p1, relu -----------------------
__global__ __launch_bounds__(128) void k_e1(const float* __restrict__ x,
                                            const float* __restrict__ w,
                                            const float* __restrict__ b) {
    __shared__ float s_in[4 * 258];
    __shared__ float s_w[512];
    const int oh = blockIdx.x, n = blockIdx.y, t = threadIdx.x;
    for (int i = t; i < 4 * 258; i += 128) {
        int r = i / 258, c = i % 258;
        int ih = 2 * oh - 1 + r, iw = c - 1;
        s_in[i] = (ih >= 0 && ih < 256 && iw >= 0 && iw < 256)
                      ? x[n * 65536 + ih * 256 + iw] : 0.f;
    }
    for (int i = t; i < 512; i += 128) s_w[i] = w[i];
    __syncthreads();
    float acc[32];
#pragma unroll
    for (int o = 0; o < 32; o++) acc[o] = 0.f;
    const int ow = t;
#pragma unroll
    for (int k = 0; k < 16; k++) {
        float v = s_in[(k >> 2) * 258 + 2 * ow + (k & 3)];
#pragma unroll
        for (int o = 0; o < 32; o++) acc[o] = fmaf(v, s_w[o * 16 + k], acc[o]);
    }
    for (int o = 0; o < 32; o++) {
        float r = __fadd_rn(acc[o], b[o]);
        g_h1[((n * 32 + o) * 128 + oh) * 128 + ow] = r > 0.f ? r : 0.f;
    }
}

// ------------------------- e2: 32->64, k4 s2 p1, relu ----------------------
// Block: one (n, oh) row, 64 ow x 64 oc. Thread: 4 ow x 4 oc (2 f32x2 pairs).
// Chain per output: (kh, kw) outer, ic 0..31 innermost — Eigen order.
__global__ __launch_bounds__(256) void k_e2(const float* __restrict__ w,
                                            const float* __restrict__ b) {
    extern __shared__ float sm[];
    float* s_in = sm;            // [ic(32)][r(4)][130] = 16640
    float* s_wk = sm + 16640;    // [ic(32)][oc(64)]    = 2048
    const int oh = blockIdx.x, n = blockIdx.y, t = threadIdx.x;
    const int tow = t & 15, tog = t >> 4;     // 4 ow, 4 oc
    for (int i = t; i < 16640; i += 256) {
        int ic = i / 520, rem = i % 520;
        int r = rem / 130, c = rem % 130;
        int ih = 2 * oh - 1 + r, iw = c - 1;
        s_in[i] = (ih >= 0 && ih < 128 && iw >= 0 && iw < 128)
                      ? g_h1[((n * 32 + ic) * 128 + ih) * 128 + iw] : 0.f;
    }
    u64 acc[4][2];
#pragma unroll
    for (int i = 0; i < 4; i++) { acc[i][0] = 0ull; acc[i][1] = 0ull; }
#pragma unroll 1
    for (int kh = 0; kh < 4; kh++) {
#pragma unroll 1
        for (int kw = 0; kw < 4; kw++) {
            __syncthreads();
            for (int i = t; i < 2048; i += 256) {
                int ic = i >> 6, oc = i & 63;
                s_wk[i] = w[((oc * 32 + ic) << 4) + kh * 4 + kw];
            }
            __syncthreads();
            const float* pin = s_in + kh * 130 + 8 * tow + kw;
#pragma unroll 4
            for (int ic = 0; ic < 32; ic++) {
                const float* q = pin + ic * 520;
                u64 w01 = *(const u64*)(s_wk + ic * 64 + tog * 4);
                u64 w23 = *(const u64*)(s_wk + ic * 64 + tog * 4 + 2);
#pragma unroll
                for (int i = 0; i < 4; i++) {
                    float v = q[2 * i];
                    u64 vv = pk2(v, v);
                    acc[i][0] = f2fma(vv, w01, acc[i][0]);
                    acc[i][1] = f2fma(vv, w23, acc[i][1]);
                }
            }
        }
    }
#pragma unroll
    for (int i = 0; i < 4; i++) {
#pragma unroll
        for (int j2 = 0; j2 < 2; j2++) {
            float2 f = upk(acc[i][j2]);
            int oc0 = tog * 4 + j2 * 2;
            float r0 = __fadd_rn(f.x, b[oc0]);
            float r1 = __fadd_rn(f.y, b[oc0 + 1]);
            int ow = 4 * tow + i;
            g_h2[((n * 64 + oc0) * 64 + oh) * 64 + ow]       = r0 > 0.f ? r0 : 0.f;
            g_h2[((n * 64 + oc0 + 1) * 64 + oh) * 64 + ow]   = r1 > 0.f ? r1 : 0.f;
        }
    }
}

// ------------------------- e3: 64->64, k3 s1 p1, relu ----------------------
__global__ __launch_bounds__(256) void k_e3(const float* __restrict__ w,
                                            const float* __restrict__ b,
                                            float* __restrict__ ze) {
    extern __shared__ float sm[];
    float* s_in = sm;            // [ic(64)][r(3)][66] = 12672
    float* s_wk = sm + 12672;    // [ic(64)][oc(64)]   = 4096
    const int oh = blockIdx.x, n = blockIdx.y, t = threadIdx.x;
    const int tow = t & 15, tog = t >> 4;
    for (int i = t; i < 12672; i += 256) {
        int ic = i / 198, rem = i % 198;
        int r = rem / 66, c = rem % 66;
        int ih = oh - 1 + r, iw = c - 1;
        s_in[i] = (ih >= 0 && ih < 64 && iw >= 0 && iw < 64)
                      ? g_h2[((n * 64 + ic) * 64 + ih) * 64 + iw] : 0.f;
    }
    u64 acc[4][2];
#pragma unroll
    for (int i = 0; i < 4; i++) { acc[i][0] = 0ull; acc[i][1] = 0ull; }
#pragma unroll 1
    for (int kh = 0; kh < 3; kh++) {
#pragma unroll 1
        for (int kw = 0; kw < 3; kw++) {
            __syncthreads();
            for (int i = t; i < 4096; i += 256) {
                int ic = i >> 6, oc = i & 63;
                s_wk[i] = w[(oc * 64 + ic) * 9 + kh * 3 + kw];
            }
            __syncthreads();
            const float* pin = s_in + kh * 66 + 4 * tow + kw;
#pragma unroll 4
            for (int ic = 0; ic < 64; ic++) {
                const float* q = pin + ic * 198;
                u64 w01 = *(const u64*)(s_wk + ic * 64 + tog * 4);
                u64 w23 = *(const u64*)(s_wk + ic * 64 + tog * 4 + 2);
#pragma unroll
                for (int i = 0; i < 4; i++) {
                    float v = q[i];
                    u64 vv = pk2(v, v);
                    acc[i][0] = f2fma(vv, w01, acc[i][0]);
                    acc[i][1] = f2fma(vv, w23, acc[i][1]);
                }
            }
        }
    }
#pragma unroll
    for (int i = 0; i < 4; i++) {
#pragma unroll
        for (int j2 = 0; j2 < 2; j2++) {
            float2 f = upk(acc[i][j2]);
            int oc0 = tog * 4 + j2 * 2;
            float r0 = __fadd_rn(f.x, b[oc0]);
            float r1 = __fadd_rn(f.y, b[oc0 + 1]);
            int ow = 4 * tow + i;
            ze[((n * 64 + oc0) * 64 + oh) * 64 + ow]     = r0 > 0.f ? r0 : 0.f;
            ze[((n * 64 + oc0 + 1) * 64 + oh) * 64 + ow] = r1 > 0.f ? r1 : 0.f;
        }
    }
}

// --------------- codebook norms + transpose --------------------------------
__global__ void k_en(const float* __restrict__ emb) {
    int k = blockIdx.x * blockDim.x + threadIdx.x;
    if (k < 512) {
        float s = 0.f;
        for (int c = 0; c < 64; c++) {
            float v = emb[k * 64 + c];
            s = __fadd_rn(s, __fmul_rn(v, v));
            g_embT[c * 512 + k] = v;
        }
        g_en[k] = s;
    }
}

// ------------------------- VQ argmin + gather ------------------------------
__global__ __launch_bounds__(256) void k_vq(const float* __restrict__ ze,
                                            const float* __restrict__ emb,
                                            float* __restrict__ zq) {
    __shared__ __align__(16) float s_z[4096];   // [c(64)][pos(64)]
    __shared__ __align__(16) float s_e[4096];   // [c(64)][code_local(64)]
    __shared__ float s_zz[64];
    __shared__ float s_en[512];
    __shared__ float s_bv[256];
    __shared__ int s_bi[256];
    __shared__ int s_idx[64];
    const int h = blockIdx.x, n = blockIdx.y, t = threadIdx.x;
    const int pos = t & 63, kg = t >> 6;
    for (int i = t; i < 4096; i += 256)
        s_z[i] = ze[(n * 64 + (i >> 6)) * 4096 + h * 64 + (i & 63)];
    for (int i = t; i < 512; i += 256) s_en[i] = g_en[i];
    __syncthreads();
    if (t < 64) {
        float a = 0.f;
        for (int c = 0; c < 64; c++) {
            float v = s_z[c * 64 + t];
            a = __fadd_rn(a, __fmul_rn(v, v));
        }
        s_zz[t] = a;
    }
    float bv = 3.4e38f;
    int bi = 0;
    for (int ch = 0; ch < 8; ch++) {
        __syncthreads();
        for (int i = t; i < 4096; i += 256)
            s_e[i] = g_embT[(i >> 6) * 512 + ch * 64 + (i & 63)];
        __syncthreads();
        const float zz = s_zz[pos];
        u64 dot[8];
#pragma unroll
        for (int j = 0; j < 8; j++) dot[j] = 0ull;
#pragma unroll 4
        for (int c = 0; c < 64; c++) {   // c ascending: Eigen gemm order
            float v = s_z[c * 64 + pos];
            u64 vv = pk2(v, v);
            const u64* pe = (const u64*)(s_e + c * 64 + kg * 16);
#pragma unroll
            for (int j = 0; j < 8; j++)
                dot[j] = f2fma(vv, pe[j], dot[j]);
        }
#pragma unroll
        for (int j = 0; j < 8; j++) {
            float2 f = upk(dot[j]);
            int code0 = ch * 64 + kg * 16 + 2 * j;
            float d0 = __fadd_rn(__fsub_rn(zz, __fmul_rn(2.0f, f.x)), s_en[code0]);
            float d1 = __fadd_rn(__fsub_rn(zz, __fmul_rn(2.0f, f.y)), s_en[code0 + 1]);
            if (d0 < bv) { bv = d0; bi = code0; }
            if (d1 < bv) { bv = d1; bi = code0 + 1; }
        }
    }
    s_bv[t] = bv;
    s_bi[t] = bi;
    __syncthreads();
    if (t < 64) {
        for (int q = 1; q < 4; q++) {
            float v2 = s_bv[t + q * 64];
            int i2 = s_bi[t + q * 64];
            if (v2 < bv || (v2 == bv && i2 < bi)) { bv = v2; bi = i2; }
        }
        s_idx[t] = bi;
    }
    __syncthreads();
    for (int i = t; i < 4096; i += 256) {
        int c = i >> 6, wq = i & 63;
        zq[(n * 64 + c) * 4096 + h * 64 + wq] = emb[s_idx[wq] * 64 + c];
    }
}

// --------------- d1: convT 64->32, k3 s1 p1, relu; in = ze+(zq-ze) ---------
// Block: 2 oh rows x 64 ow x 32 oc. Thread: 1 oh x 4 ow x 4 oc.
__global__ __launch_bounds__(256) void k_d1(const float* __restrict__ ze,
                                            const float* __restrict__ zq,
                                            const float* __restrict__ w,
                                            const float* __restrict__ b) {
    extern __shared__ float sm[];
    float* s_in = sm;            // [ic(64)][r(4)][66] = 16896
    float* s_wk = sm + 16896;    // [ic(64)][oc(32)]   = 2048
    const int oh0 = blockIdx.x * 2, n = blockIdx.y, t = threadIdx.x;
    const int tow = t & 15, toh = (t >> 4) & 1, tog = t >> 5;   // 4ow,1oh,4oc
    for (int i = t; i < 16896; i += 256) {
        int ic = i / 264, rem = i % 264;
        int r = rem / 66, c = rem % 66;
        int ih = oh0 - 1 + r, iw = c - 1;
        float v = 0.f;
        if (ih >= 0 && ih < 64 && iw >= 0 && iw < 64) {
            int off = ((n * 64 + ic) * 64 + ih) * 64 + iw;
            float a = ze[off], q = zq[off];
            v = __fadd_rn(a, __fsub_rn(q, a));
        }
        s_in[i] = v;
    }
    u64 acc[4][2];
#pragma unroll
    for (int i = 0; i < 4; i++) { acc[i][0] = 0ull; acc[i][1] = 0ull; }
#pragma unroll 1
    for (int kh = 0; kh < 3; kh++) {
#pragma unroll 1
        for (int kw = 0; kw < 3; kw++) {
            __syncthreads();
            for (int i = t; i < 2048; i += 256) {
                int ic = i >> 5, oc = i & 31;
                s_wk[i] = w[(ic * 32 + oc) * 9 + 8 - (kh * 3 + kw)];
            }
            __syncthreads();
            const float* pin = s_in + (toh + kh) * 66 + 4 * tow + kw;
#pragma unroll 4
            for (int ic = 0; ic < 64; ic++) {
                const float* q = pin + ic * 264;
                u64 w01 = *(const u64*)(s_wk + ic * 32 + tog * 4);
                u64 w23 = *(const u64*)(s_wk + ic * 32 + tog * 4 + 2);
#pragma unroll
                for (int i = 0; i < 4; i++) {
                    float v = q[i];
                    u64 vv = pk2(v, v);
                    acc[i][0] = f2fma(vv, w01, acc[i][0]);
                    acc[i][1] = f2fma(vv, w23, acc[i][1]);
                }
            }
        }
    }
    const int oh = oh0 + toh;
#pragma unroll
    for (int i = 0; i < 4; i++) {
#pragma unroll
        for (int j2 = 0; j2 < 2; j2++) {
            float2 f = upk(acc[i][j2]);
            int oc0 = tog * 4 + j2 * 2;
            float r0 = f.x + b[oc0];
            float r1 = f.y + b[oc0 + 1];
            int ow = 4 * tow + i;
            g_d1o[((n * 32 + oc0) * 64 + oh) * 64 + ow]     = r0 > 0.f ? r0 : 0.f;
            g_d1o[((n * 32 + oc0 + 1) * 64 + oh) * 64 + ow] = r1 > 0.f ? r1 : 0.f;
        }
    }
}

// --------------- d2: convT 32->64, k4 s2 p1, relu (parity-decomposed) ------
// Block: 1 oh x 128 ow x 64 oc. Thread: 4 ow (same parity) x 8 oc.
__global__ __launch_bounds__(256) void k_d2(const float* __restrict__ w,
                                            const float* __restrict__ b) {
    __shared__ __align__(16) float s_in[16 * 132];   // [ic(16)][r(2)][66]
    __shared__ __align__(16) float s_w[8192];        // [ic(16)][r(2)][kw(4)][oc(64)]
    const int oh = blockIdx.x, n = blockIdx.y, t = threadIdx.x;
    const int p = t & 1, u = (t >> 1) & 15, tog = t >> 5;   // parity, 4 ow, 8 oc
    const int kh_a = 1 - (oh & 1);
    const int ih_a = (oh + 1 - kh_a) >> 1;
    const int kw_a = 1 - p;
    u64 acc[4][4];
#pragma unroll
    for (int i = 0; i < 4; i++)
#pragma unroll
        for (int j = 0; j < 4; j++) acc[i][j] = 0ull;
#pragma unroll 1
    for (int cc = 0; cc < 2; cc++) {
        __syncthreads();
        for (int i = t; i < 2112; i += 256) {
            int ic = i / 132, rem = i % 132;
            int r = rem / 66, c = rem % 66;
            int ih = (r == 0) ? ih_a : ih_a - 1;
            int iw = c - 1;
            s_in[i] = (ih >= 0 && ih < 64 && iw >= 0 && iw < 64)
                          ? g_d1o[((n * 32 + cc * 16 + ic) * 64 + ih) * 64 + iw] : 0.f;
        }
        for (int i = t; i < 8192; i += 256) {
            int ic = i >> 9, rem = i & 511;
            int r = rem >> 8, kw = (rem >> 6) & 3, oc = rem & 63;
            s_w[i] = w[(((cc * 16 + ic) * 64 + oc) << 4) + (kh_a + 2 * r) * 4 + kw];
        }
        __syncthreads();
#pragma unroll 2
        for (int ic = 0; ic < 16; ic++) {
#pragma unroll
            for (int r = 0; r < 2; r++) {
#pragma unroll
                for (int m = 0; m < 2; m++) {
                    int kw = kw_a + 2 * m;
                    const u64* pw = (const u64*)(s_w + ((ic * 2 + r) * 4 + kw) * 64 + tog * 8);
                    const float* q = s_in + ic * 132 + r * 66 + 4 * u + p - m + 1;
#pragma unroll
                    for (int i = 0; i < 4; i++) {
                        float v = q[i];
                        u64 vv = pk2(v, v);
                        acc[i][0] = f2fma(vv, pw[0], acc[i][0]);
                        acc[i][1] = f2fma(vv, pw[1], acc[i][1]);
                        acc[i][2] = f2fma(vv, pw[2], acc[i][2]);
                        acc[i][3] = f2fma(vv, pw[3], acc[i][3]);
                    }
                }
            }
        }
    }
#pragma unroll
    for (int i = 0; i < 4; i++) {
        int ow = 2 * (4 * u + i) + p;
#pragma unroll
        for (int j = 0; j < 4; j++) {
            float2 f = upk(acc[i][j]);
            int oc0 = tog * 8 + 2 * j;
            float r0 = f.x + b[oc0];
            float r1 = f.y + b[oc0 + 1];
            g_d2o[((n * 64 + oc0) * 128 + oh) * 128 + ow]     = r0 > 0.f ? r0 : 0.f;
            g_d2o[((n * 64 + oc0 + 1) * 128 + oh) * 128 + ow] = r1 > 0.f ? r1 : 0.f;
        }
    }
}

// --------------- d3: convT 64->1, k4 s2 p1 (no relu) -----------------------
__global__ __launch_bounds__(256) void k_d3(const float* __restrict__ w,
                                            const float* __restrict__ bb,
                                            float* __restrict__ xh) {
    __shared__ float s_in[32 * 260];
    __shared__ float s_w[512];
    const int oh = blockIdx.x, n = blockIdx.y, t = threadIdx.x;
    const int ow = t;
    const int kh_a = 1 - (oh & 1);
    const int ih_a = (oh + 1 - kh_a) >> 1;
    const int ih_b = ih_a - 1;
    const int kw_a = 1 - (ow & 1);
    const int iw_a = (ow + 1 - kw_a) >> 1;
    for (int i = t; i < 512; i += 256) {
        int ic = i >> 3, r = (i >> 2) & 1, kw = i & 3;
        int kh = kh_a + 2 * r;
        s_w[i] = w[ic * 16 + kh * 4 + kw];
    }
    float acc = 0.f;
    for (int cc = 0; cc < 2; cc++) {
        __syncthreads();
        for (int i = t; i < 8320; i += 256) {
            int ic = i / 260, rem = i % 260;
            int r = rem / 130, c = rem % 130;
            int ih = (r == 0) ? ih_a : ih_b;
            int iw = c - 1;
            s_in[i] = (ih >= 0 && ih < 128 && iw >= 0 && iw < 128)
                          ? g_d2o[((n * 64 + cc * 32 + ic) * 128 + ih) * 128 + iw] : 0.f;
        }
        __syncthreads();
        for (int ic = 0; ic < 32; ic++) {
#pragma unroll
            for (int r = 0; r < 2; r++) {
#pragma unroll
                for (int m = 0; m < 2; m++) {
                    float v = s_in[ic * 260 + r * 130 + iw_a - m + 1];
                    acc = fmaf(v, s_w[((cc * 32 + ic) << 3) + r * 4 + kw_a + 2 * m], acc);
                }
            }
        }
    }
    xh[n * 65536 + oh * 256 + ow] = __fadd_rn(acc, bb[0]);
}

// ---------------------------------------------------------------------------
extern "C" void kernel_launch(void* const* d_in, const int* in_sizes, int n_in,
                              void* d_out, int out_size) {
    const float* x   = (const float*)d_in[0];
    const float* e1w = (const float*)d_in[1];
    const float* e1b = (const float*)d_in[2];
    const float* e2w = (const float*)d_in[3];
    const float* e2b = (const float*)d_in[4];
    const float* e3w = (const float*)d_in[5];
    const float* e3b = (const float*)d_in[6];
    const float* emb = (const float*)d_in[7];
    const float* d1w = (const float*)d_in[8];
    const float* d1b = (const float*)d_in[9];
    const float* d2w = (const float*)d_in[10];
    const float* d2b = (const float*)d_in[11];
    const float* d3w = (const float*)d_in[12];
    const float* d3b = (const float*)d_in[13];

    float* out = (float*)d_out;
    float* xh = out;
    float* ze = out + 4194304;
    float* zq = out + 4194304 + 16777216;

    static bool attr_done = false;
    if (!attr_done) {
        cudaFuncSetAttribute(k_e2, cudaFuncAttributeMaxDynamicSharedMemorySize, 74752);
        cudaFuncSetAttribute(k_e3, cudaFuncAttributeMaxDynamicSharedMemorySize, 67072);
        cudaFuncSetAttribute(k_d1, cudaFuncAttributeMaxDynamicSharedMemorySize, 75776);
        attr_done = true;
    }

    k_e1<<<dim3(128, 64), 128>>>(x, e1w, e1b);
    k_e2<<<dim3(64, 64), 256, 74752>>>(e2w, e2b);
    k_e3<<<dim3(64, 64), 256, 67072>>>(e3w, e3b, ze);
    k_en<<<2, 256>>>(emb);
    k_vq<<<dim3(64, 64), 256>>>(ze, emb, zq);
    k_d1<<<dim3(32, 64), 256, 75776>>>(ze, zq, d1w, d1b);
    k_d2<<<dim3(128, 64), 256>>>(d2w, d2b);
    k_d3<<<dim3(256, 64), 256>>>(d3w, d3b, xh);
}

// round 4
// speedup vs baseline: 1.1423x; 1.0392x over previous
#include <cuda_runtime.h>

// ---------------------------------------------------------------------------
// VQ-VAE forward, fp32, Eigen-chain-order-exact encoder/VQ, f32x2-packed FMA.
// Round 4: division-free staging, per-kh weight phases, LDS.128 weight loads.
// ---------------------------------------------------------------------------

typedef unsigned long long u64;

__device__ float g_h1[64 * 32 * 128 * 128];
__device__ float g_h2[64 * 64 * 64 * 64];
__device__ float g_d1o[64 * 32 * 64 * 64];
__device__ float g_d2o[64 * 64 * 128 * 128];
__device__ float g_en[512];
__device__ float g_embT[64 * 512];   // [c][code]

__device__ __forceinline__ u64 pk2(float x, float y) {
    u64 r; asm("mov.b64 %0, {%1, %2};" : "=l"(r) : "f"(x), "f"(y)); return r;
}
__device__ __forceinline__ u64 f2fma(u64 a, u64 b, u64 c) {
    u64 d; asm("fma.rn.f32x2 %0, %1, %2, %3;" : "=l"(d) : "l"(a), "l"(b), "l"(c)); return d;
}
__device__ __forceinline__ float2 upk(u64 v) {
    float2 f; asm("mov.b64 {%0, %1}, %2;" : "=f"(f.x), "=f"(f.y) : "l"(v)); return f;
}

// --------------- codebook norms + transpose (launched FIRST) ---------------
__global__ void k_en(const float* __restrict__ emb) {
    int k = blockIdx.x * blockDim.x + threadIdx.x;
    if (k < 512) {
        float s = 0.f;
        for (int c = 0; c < 64; c++) {
            float v = emb[k * 64 + c];
            s = __fadd_rn(s, __fmul_rn(v, v));
            g_embT[c * 512 + k] = v;
        }
        g_en[k] = s;
    }
}

// ------------------------- e1: 1->32, k4 s2 p1, relu -----------------------
__global__ __launch_bounds__(128) void k_e1(const float* __restrict__ x,
                                            const float* __restrict__ w,
                                            const float* __restrict__ b) {
    __shared__ float s_in[4 * 258];
    __shared__ float s_w[512];
    const int oh = blockIdx.x, n = blockIdx.y, t = threadIdx.x;
    const int lane = t & 31, wrp = t >> 5;    // 4 warps
    {
        int r = wrp;
        int ih = 2 * oh - 1 + r;
        bool rowok = (ih >= 0 && ih < 256);
        const float* src = x + n * 65536 + ih * 256;
        float* dst = s_in + r * 258;
#pragma unroll
        for (int k = 0; k < 9; k++) {
            int c = lane + 32 * k;
            if (c < 258) {
                int iw = c - 1;
                dst[c] = (rowok && iw >= 0 && iw < 256) ? src[iw] : 0.f;
            }
        }
    }
    for (int i = t; i < 512; i += 128) s_w[i] = w[i];
    __syncthreads();
    float acc[32];
#pragma unroll
    for (int o = 0; o < 32; o++) acc[o] = 0.f;
    const int ow = t;
#pragma unroll
    for (int k = 0; k < 16; k++) {
        float v = s_in[(k >> 2) * 258 + 2 * ow + (k & 3)];
#pragma unroll
        for (int o = 0; o < 32; o++) acc[o] = fmaf(v, s_w[o * 16 + k], acc[o]);
    }
    for (int o = 0; o < 32; o++) {
        float r = __fadd_rn(acc[o], b[o]);
        g_h1[((n * 32 + o) * 128 + oh) * 128 + ow] = r > 0.f ? r : 0.f;
    }
}

// ------------------------- e2: 32->64, k4 s2 p1, relu ----------------------
// smem: s_in [r(4)][ic(32)][130] = 16640 ; s_w per-kh [kw(4)][ic(32)][oc(64)] = 8192
// Thread: 4 ow x 4 oc. Chain: kh, kw outer; ic 0..31 innermost (Eigen).
__global__ __launch_bounds__(256) void k_e2(const float* __restrict__ w,
                                            const float* __restrict__ b) {
    extern __shared__ float sm[];
    float* s_in = sm;            // 16640
    float* s_w  = sm + 16640;    // 8192
    const int oh = blockIdx.x, n = blockIdx.y, t = threadIdx.x;
    const int tow = t & 15, tog = t >> 4;
    const int lane = t & 31, wrp = t >> 5;
#pragma unroll 1
    for (int m = 0; m < 16; m++) {           // 128 rows = [r4][ic32], 16/warp
        int row = wrp * 16 + m;
        int r = row >> 5, ic = row & 31;
        int ih = 2 * oh - 1 + r;
        bool rowok = (ih >= 0 && ih < 128);
        const float* src = g_h1 + ((n * 32 + ic) * 128 + ih) * 128;
        float* dst = s_in + row * 130;
#pragma unroll
        for (int k = 0; k < 5; k++) {
            int c = lane + 32 * k;
            if (c < 130) {
                int iw = c - 1;
                dst[c] = (rowok && iw >= 0 && iw < 128) ? src[iw] : 0.f;
            }
        }
    }
    u64 acc[4][2];
#pragma unroll
    for (int i = 0; i < 4; i++) { acc[i][0] = 0ull; acc[i][1] = 0ull; }
#pragma unroll 1
    for (int kh = 0; kh < 4; kh++) {
        __syncthreads();
        for (int i = t; i < 8192; i += 256) {
            int kw = i >> 11, ic = (i >> 6) & 31, oc = i & 63;
            s_w[i] = w[((oc * 32 + ic) << 4) + (kh << 2) + kw];
        }
        __syncthreads();
#pragma unroll
        for (int kw = 0; kw < 4; kw++) {
            const float* pin = s_in + kh * 4160 + 8 * tow + kw;
            const float* pw = s_w + (kw << 11) + (tog << 2);
#pragma unroll 4
            for (int ic = 0; ic < 32; ic++) {
                ulonglong2 wp = *(const ulonglong2*)(pw + (ic << 6));
                const float* q = pin + ic * 130;
#pragma unroll
                for (int i = 0; i < 4; i++) {
                    float v = q[2 * i];
                    u64 vv = pk2(v, v);
                    acc[i][0] = f2fma(vv, wp.x, acc[i][0]);
                    acc[i][1] = f2fma(vv, wp.y, acc[i][1]);
                }
            }
        }
    }
#pragma unroll
    for (int i = 0; i < 4; i++) {
#pragma unroll
        for (int j2 = 0; j2 < 2; j2++) {
            float2 f = upk(acc[i][j2]);
            int oc0 = tog * 4 + j2 * 2;
            float r0 = __fadd_rn(f.x, b[oc0]);
            float r1 = __fadd_rn(f.y, b[oc0 + 1]);
            int ow = 4 * tow + i;
            g_h2[((n * 64 + oc0) * 64 + oh) * 64 + ow]     = r0 > 0.f ? r0 : 0.f;
            g_h2[((n * 64 + oc0 + 1) * 64 + oh) * 64 + ow] = r1 > 0.f ? r1 : 0.f;
        }
    }
}

// ------------------------- e3: 64->64, k3 s1 p1, relu ----------------------
// smem: s_in [r(3)][ic(64)][66] = 12672 ; s_w per-kh [kw(3)][ic(64)][oc(64)] = 12288
__global__ __launch_bounds__(256) void k_e3(const float* __restrict__ w,
                                            const float* __restrict__ b,
                                            float* __restrict__ ze) {
    extern __shared__ float sm[];
    float* s_in = sm;            // 12672
    float* s_w  = sm + 12672;    // 12288
    const int oh = blockIdx.x, n = blockIdx.y, t = threadIdx.x;
    const int tow = t & 15, tog = t >> 4;
    const int lane = t & 31, wrp = t >> 5;
#pragma unroll 1
    for (int m = 0; m < 24; m++) {           // 192 rows = [r3][ic64], 24/warp
        int row = wrp * 24 + m;
        int r = row >> 6, ic = row & 63;
        int ih = oh - 1 + r;
        bool rowok = (ih >= 0 && ih < 64);
        const float* src = g_h2 + ((n * 64 + ic) * 64 + ih) * 64;
        float* dst = s_in + row * 66;
#pragma unroll
        for (int k = 0; k < 3; k++) {
            int c = lane + 32 * k;
            if (c < 66) {
                int iw = c - 1;
                dst[c] = (rowok && iw >= 0 && iw < 64) ? src[iw] : 0.f;
            }
        }
    }
    u64 acc[4][2];
#pragma unroll
    for (int i = 0; i < 4; i++) { acc[i][0] = 0ull; acc[i][1] = 0ull; }
#pragma unroll 1
    for (int kh = 0; kh < 3; kh++) {
        __syncthreads();
        for (int i = t; i < 12288; i += 256) {
            int kw = i >> 12, ic = (i >> 6) & 63, oc = i & 63;
            s_w[i] = w[(oc * 64 + ic) * 9 + kh * 3 + kw];
        }
        __syncthreads();
#pragma unroll
        for (int kw = 0; kw < 3; kw++) {
            const float* pin = s_in + kh * 4224 + 4 * tow + kw;
            const float* pw = s_w + (kw << 12) + (tog << 2);
#pragma unroll 4
            for (int ic = 0; ic < 64; ic++) {
                ulonglong2 wp = *(const ulonglong2*)(pw + (ic << 6));
                const float* q = pin + ic * 66;
#pragma unroll
                for (int i = 0; i < 4; i++) {
                    float v = q[i];
                    u64 vv = pk2(v, v);
                    acc[i][0] = f2fma(vv, wp.x, acc[i][0]);
                    acc[i][1] = f2fma(vv, wp.y, acc[i][1]);
                }
            }
        }
    }
#pragma unroll
    for (int i = 0; i < 4; i++) {
#pragma unroll
        for (int j2 = 0; j2 < 2; j2++) {
            float2 f = upk(acc[i][j2]);
            int oc0 = tog * 4 + j2 * 2;
            float r0 = __fadd_rn(f.x, b[oc0]);
            float r1 = __fadd_rn(f.y, b[oc0 + 1]);
            int ow = 4 * tow + i;
            ze[((n * 64 + oc0) * 64 + oh) * 64 + ow]     = r0 > 0.f ? r0 : 0.f;
            ze[((n * 64 + oc0 + 1) * 64 + oh) * 64 + ow] = r1 > 0.f ? r1 : 0.f;
        }
    }
}

// ------------------------- VQ argmin + gather ------------------------------
__global__ __launch_bounds__(256) void k_vq(const float* __restrict__ ze,
                                            const float* __restrict__ emb,
                                            float* __restrict__ zq) {
    __shared__ __align__(16) float s_z[4096];   // [c(64)][pos(64)]
    __shared__ __align__(16) float s_e[4096];   // [c(64)][code_local(64)]
    __shared__ float s_zz[64];
    __shared__ float s_en[512];
    __shared__ float s_bv[256];
    __shared__ int s_bi[256];
    __shared__ int s_idx[64];
    const int h = blockIdx.x, n = blockIdx.y, t = threadIdx.x;
    const int pos = t & 63, kg = t >> 6;
    for (int i = t; i < 4096; i += 256)
        s_z[i] = ze[(n * 64 + (i >> 6)) * 4096 + h * 64 + (i & 63)];
    for (int i = t; i < 512; i += 256) s_en[i] = g_en[i];
    __syncthreads();
    if (t < 64) {
        float a = 0.f;
        for (int c = 0; c < 64; c++) {
            float v = s_z[c * 64 + t];
            a = __fadd_rn(a, __fmul_rn(v, v));
        }
        s_zz[t] = a;
    }
    float bv = 3.4e38f;
    int bi = 0;
    for (int ch = 0; ch < 8; ch++) {
        __syncthreads();
        for (int i = t; i < 4096; i += 256)
            s_e[i] = g_embT[(i >> 6) * 512 + ch * 64 + (i & 63)];
        __syncthreads();
        const float zz = s_zz[pos];
        u64 dot[8];
#pragma unroll
        for (int j = 0; j < 8; j++) dot[j] = 0ull;
#pragma unroll 4
        for (int c = 0; c < 64; c++) {
            float v = s_z[c * 64 + pos];
            u64 vv = pk2(v, v);
            const ulonglong2* pe = (const ulonglong2*)(s_e + c * 64 + kg * 16);
#pragma unroll
            for (int j = 0; j < 4; j++) {
                ulonglong2 e2v = pe[j];
                dot[2 * j]     = f2fma(vv, e2v.x, dot[2 * j]);
                dot[2 * j + 1] = f2fma(vv, e2v.y, dot[2 * j + 1]);
            }
        }
#pragma unroll
        for (int j = 0; j < 8; j++) {
            float2 f = upk(dot[j]);
            int code0 = ch * 64 + kg * 16 + 2 * j;
            float d0 = __fadd_rn(__fsub_rn(zz, __fmul_rn(2.0f, f.x)), s_en[code0]);
            float d1 = __fadd_rn(__fsub_rn(zz, __fmul_rn(2.0f, f.y)), s_en[code0 + 1]);
            if (d0 < bv) { bv = d0; bi = code0; }
            if (d1 < bv) { bv = d1; bi = code0 + 1; }
        }
    }
    s_bv[t] = bv;
    s_bi[t] = bi;
    __syncthreads();
    if (t < 64) {
        for (int q = 1; q < 4; q++) {
            float v2 = s_bv[t + q * 64];
            int i2 = s_bi[t + q * 64];
            if (v2 < bv || (v2 == bv && i2 < bi)) { bv = v2; bi = i2; }
        }
        s_idx[t] = bi;
    }
    __syncthreads();
    for (int i = t; i < 4096; i += 256) {
        int c = i >> 6, wq = i & 63;
        zq[(n * 64 + c) * 4096 + h * 64 + wq] = emb[s_idx[wq] * 64 + c];
    }
}

// --------------- d1: convT 64->32, k3 s1 p1, relu; in = ze+(zq-ze) ---------
// smem: s_in [r(4)][ic(64)][66] = 16896 ; s_w per-kh [kw(3)][ic(64)][oc(32)] = 6144
__global__ __launch_bounds__(256) void k_d1(const float* __restrict__ ze,
                                            const float* __restrict__ zq,
                                            const float* __restrict__ w,
                                            const float* __restrict__ b) {
    extern __shared__ float sm[];
    float* s_in = sm;            // 16896
    float* s_w  = sm + 16896;    // 6144
    const int oh0 = blockIdx.x * 2, n = blockIdx.y, t = threadIdx.x;
    const int tow = t & 15, toh = (t >> 4) & 1, tog = t >> 5;
    const int lane = t & 31, wrp = t >> 5;
#pragma unroll 1
    for (int m = 0; m < 32; m++) {           // 256 rows = [r4][ic64], 32/warp
        int row = wrp * 32 + m;
        int r = row >> 6, ic = row & 63;
        int ih = oh0 - 1 + r;
        bool rowok = (ih >= 0 && ih < 64);
        const float* pz = ze + ((n * 64 + ic) * 64 + ih) * 64;
        const float* pq = zq + ((n * 64 + ic) * 64 + ih) * 64;
        float* dst = s_in + row * 66;
#pragma unroll
        for (int k = 0; k < 3; k++) {
            int c = lane + 32 * k;
            if (c < 66) {
                int iw = c - 1;
                float v = 0.f;
                if (rowok && iw >= 0 && iw < 64) {
                    float a = pz[iw], q = pq[iw];
                    v = __fadd_rn(a, __fsub_rn(q, a));
                }
                dst[c] = v;
            }
        }
    }
    u64 acc[4][2];
#pragma unroll
    for (int i = 0; i < 4; i++) { acc[i][0] = 0ull; acc[i][1] = 0ull; }
#pragma unroll 1
    for (int kh = 0; kh < 3; kh++) {
        __syncthreads();
        for (int i = t; i < 6144; i += 256) {
            int kw = i >> 11, ic = (i >> 5) & 63, oc = i & 31;
            s_w[i] = w[(ic * 32 + oc) * 9 + 8 - kh * 3 - kw];
        }
        __syncthreads();
#pragma unroll
        for (int kw = 0; kw < 3; kw++) {
            const float* pin = s_in + (toh + kh) * 4224 + 4 * tow + kw;
            const float* pw = s_w + (kw << 11) + (tog << 2);
#pragma unroll 4
            for (int ic = 0; ic < 64; ic++) {
                ulonglong2 wp = *(const ulonglong2*)(pw + (ic << 5));
                const float* q = pin + ic * 66;
#pragma unroll
                for (int i = 0; i < 4; i++) {
                    float v = q[i];
                    u64 vv = pk2(v, v);
                    acc[i][0] = f2fma(vv, wp.x, acc[i][0]);
                    acc[i][1] = f2fma(vv, wp.y, acc[i][1]);
                }
            }
        }
    }
    const int oh = oh0 + toh;
#pragma unroll
    for (int i = 0; i < 4; i++) {
#pragma unroll
        for (int j2 = 0; j2 < 2; j2++) {
            float2 f = upk(acc[i][j2]);
            int oc0 = tog * 4 + j2 * 2;
            float r0 = f.x + b[oc0];
            float r1 = f.y + b[oc0 + 1];
            int ow = 4 * tow + i;
            g_d1o[((n * 32 + oc0) * 64 + oh) * 64 + ow]     = r0 > 0.f ? r0 : 0.f;
            g_d1o[((n * 32 + oc0 + 1) * 64 + oh) * 64 + ow] = r1 > 0.f ? r1 : 0.f;
        }
    }
}

// --------------- d2: convT 32->64, k4 s2 p1, relu (parity-decomposed) ------
__global__ __launch_bounds__(256) void k_d2(const float* __restrict__ w,
                                            const float* __restrict__ b) {
    __shared__ __align__(16) float s_in[2112];   // [r(2)][ic(16)][66]
    __shared__ __align__(16) float s_w[8192];    // [ic(16)][r(2)][kw(4)][oc(64)]
    const int oh = blockIdx.x, n = blockIdx.y, t = threadIdx.x;
    const int p = t & 1, u = (t >> 1) & 15, tog = t >> 5;
    const int lane = t & 31, wrp = t >> 5;
    const int kh_a = 1 - (oh & 1);
    const int ih_a = (oh + 1 - kh_a) >> 1;
    const int kw_a = 1 - p;
    u64 acc[4][4];
#pragma unroll
    for (int i = 0; i < 4; i++)
#pragma unroll
        for (int j = 0; j < 4; j++) acc[i][j] = 0ull;
#pragma unroll 1
    for (int cc = 0; cc < 2; cc++) {
        __syncthreads();
#pragma unroll
        for (int m = 0; m < 4; m++) {        // 32 rows = [r2][ic16], 4/warp
            int row = wrp * 4 + m;
            int r = row >> 4, ic = row & 15;
            int ih = (r == 0) ? ih_a : ih_a - 1;
            bool rowok = (ih >= 0 && ih < 64);
            const float* src = g_d1o + ((n * 32 + cc * 16 + ic) * 64 + ih) * 64;
            float* dst = s_in + row * 66;
#pragma unroll
            for (int k = 0; k < 3; k++) {
                int c = lane + 32 * k;
                if (c < 66) {
                    int iw = c - 1;
                    dst[c] = (rowok && iw >= 0 && iw < 64) ? src[iw] : 0.f;
                }
            }
        }
        for (int i = t; i < 8192; i += 256) {
            int ic = i >> 9, rem = i & 511;
            int r = rem >> 8, kw = (rem >> 6) & 3, oc = rem & 63;
            s_w[i] = w[(((cc * 16 + ic) * 64 + oc) << 4) + (kh_a + 2 * r) * 4 + kw];
        }
        __syncthreads();
#pragma unroll 2
        for (int ic = 0; ic < 16; ic++) {
#pragma unroll
            for (int r = 0; r < 2; r++) {
#pragma unroll
                for (int m = 0; m < 2; m++) {
                    int kw = kw_a + 2 * m;
                    const ulonglong2* pw = (const ulonglong2*)(s_w + ((ic * 2 + r) * 4 + kw) * 64 + tog * 8);
                    const float* q = s_in + r * 1056 + ic * 66 + 4 * u + p - m + 1;
                    ulonglong2 w01 = pw[0], w23 = pw[1];
#pragma unroll
                    for (int i = 0; i < 4; i++) {
                        float v = q[i];
                        u64 vv = pk2(v, v);
                        acc[i][0] = f2fma(vv, w01.x, acc[i][0]);
                        acc[i][1] = f2fma(vv, w01.y, acc[i][1]);
                        acc[i][2] = f2fma(vv, w23.x, acc[i][2]);
                        acc[i][3] = f2fma(vv, w23.y, acc[i][3]);
                    }
                }
            }
        }
    }
#pragma unroll
    for (int i = 0; i < 4; i++) {
        int ow = 2 * (4 * u + i) + p;
#pragma unroll
        for (int j = 0; j < 4; j++) {
            float2 f = upk(acc[i][j]);
            int oc0 = tog * 8 + 2 * j;
            float r0 = f.x + b[oc0];
            float r1 = f.y + b[oc0 + 1];
            g_d2o[((n * 64 + oc0) * 128 + oh) * 128 + ow]     = r0 > 0.f ? r0 : 0.f;
            g_d2o[((n * 64 + oc0 + 1) * 128 + oh) * 128 + ow] = r1 > 0.f ? r1 : 0.f;
        }
    }
}

// --------------- d3: convT 64->1, k4 s2 p1 (no relu) -----------------------
__global__ __launch_bounds__(256) void k_d3(const float* __restrict__ w,
                                            const float* __restrict__ bb,
                                            float* __restrict__ xh) {
    __shared__ float s_in[8320];   // [r(2)][ic(32)][130]
    __shared__ float s_w[512];
    const int oh = blockIdx.x, n = blockIdx.y, t = threadIdx.x;
    const int ow = t;
    const int lane = t & 31, wrp = t >> 5;
    const int kh_a = 1 - (oh & 1);
    const int ih_a = (oh + 1 - kh_a) >> 1;
    const int ih_b = ih_a - 1;
    const int kw_a = 1 - (ow & 1);
    const int iw_a = (ow + 1 - kw_a) >> 1;
    for (int i = t; i < 512; i += 256) {
        int ic = i >> 3, r = (i >> 2) & 1, kw = i & 3;
        int kh = kh_a + 2 * r;
        s_w[i] = w[ic * 16 + kh * 4 + kw];
    }
    float acc = 0.f;
#pragma unroll 1
    for (int cc = 0; cc < 2; cc++) {
        __syncthreads();
#pragma unroll
        for (int m = 0; m < 8; m++) {        // 64 rows = [r2][ic32], 8/warp
            int row = wrp * 8 + m;
            int r = row >> 5, ic = row & 31;
            int ih = (r == 0) ? ih_a : ih_b;
            bool rowok = (ih >= 0 && ih < 128);
            const float* src = g_d2o + ((n * 64 + cc * 32 + ic) * 128 + ih) * 128;
            float* dst = s_in + row * 130;
#pragma unroll
            for (int k = 0; k < 5; k++) {
                int c = lane + 32 * k;
                if (c < 130) {
                    int iw = c - 1;
                    dst[c] = (rowok && iw >= 0 && iw < 128) ? src[iw] : 0.f;
                }
            }
        }
        __syncthreads();
#pragma unroll 4
        for (int ic = 0; ic < 32; ic++) {
#pragma unroll
            for (int r = 0; r < 2; r++) {
#pragma unroll
                for (int m = 0; m < 2; m++) {
                    float v = s_in[r * 4160 + ic * 130 + iw_a - m + 1];
                    acc = fmaf(v, s_w[((cc * 32 + ic) << 3) + r * 4 + kw_a + 2 * m], acc);
                }
            }
        }
    }
    xh[n * 65536 + oh * 256 + ow] = __fadd_rn(acc, bb[0]);
}

// ---------------------------------------------------------------------------
extern "C" void kernel_launch(void* const* d_in, const int* in_sizes, int n_in,
                              void* d_out, int out_size) {
    const float* x   = (const float*)d_in[0];
    const float* e1w = (const float*)d_in[1];
    const float* e1b = (const float*)d_in[2];
    const float* e2w = (const float*)d_in[3];
    const float* e2b = (const float*)d_in[4];
    const float* e3w = (const float*)d_in[5];
    const float* e3b = (const float*)d_in[6];
    const float* emb = (const float*)d_in[7];
    const float* d1w = (const float*)d_in[8];
    const float* d1b = (const float*)d_in[9];
    const float* d2w = (const float*)d_in[10];
    const float* d2b = (const float*)d_in[11];
    const float* d3w = (const float*)d_in[12];
    const float* d3b = (const float*)d_in[13];

    float* out = (float*)d_out;
    float* xh = out;
    float* ze = out + 4194304;
    float* zq = out + 4194304 + 16777216;

    static bool attr_done = false;
    if (!attr_done) {
        cudaFuncSetAttribute(k_e2, cudaFuncAttributeMaxDynamicSharedMemorySize, 99328);
        cudaFuncSetAttribute(k_e3, cudaFuncAttributeMaxDynamicSharedMemorySize, 99840);
        cudaFuncSetAttribute(k_d1, cudaFuncAttributeMaxDynamicSharedMemorySize, 92160);
        attr_done = true;
    }

    k_en<<<2, 256>>>(emb);                       // first: independent of encoder
    k_e1<<<dim3(128, 64), 128>>>(x, e1w, e1b);
    k_e2<<<dim3(64, 64), 256, 99328>>>(e2w, e2b);
    k_e3<<<dim3(64, 64), 256, 99840>>>(e3w, e3b, ze);
    k_vq<<<dim3(64, 64), 256>>>(ze, emb, zq);
    k_d1<<<dim3(32, 64), 256, 92160>>>(ze, zq, d1w, d1b);
    k_d2<<<dim3(128, 64), 256>>>(d2w, d2b);
    k_d3<<<dim3(256, 64), 256>>>(d3w, d3b, xh);
}

// round 5
// speedup vs baseline: 1.7255x; 1.5106x over previous
#include <cuda_runtime.h>

// ---------------------------------------------------------------------------
// VQ-VAE forward, fp32, Eigen-chain-order-exact encoder/VQ, f32x2-packed FMA.
// Round 5: conflict-free strided-ow LDS, 8 oc/thread (halved LDS bytes/MAC).
// ---------------------------------------------------------------------------

typedef unsigned long long u64;

__device__ float g_h1[64 * 32 * 128 * 128];
__device__ float g_h2[64 * 64 * 64 * 64];
__device__ float g_d1o[64 * 32 * 64 * 64];
__device__ float g_d2o[64 * 64 * 128 * 128];
__device__ float g_en[512];
__device__ float g_embT[64 * 512];   // [c][code]

__device__ __forceinline__ u64 pk2(float x, float y) {
    u64 r; asm("mov.b64 %0, {%1, %2};" : "=l"(r) : "f"(x), "f"(y)); return r;
}
__device__ __forceinline__ u64 f2fma(u64 a, u64 b, u64 c) {
    u64 d; asm("fma.rn.f32x2 %0, %1, %2, %3;" : "=l"(d) : "l"(a), "l"(b), "l"(c)); return d;
}
__device__ __forceinline__ float2 upk(u64 v) {
    float2 f; asm("mov.b64 {%0, %1}, %2;" : "=f"(f.x), "=f"(f.y) : "l"(v)); return f;
}

// --------------- codebook norms + transpose --------------------------------
__global__ void k_en(const float* __restrict__ emb) {
    int k = blockIdx.x * blockDim.x + threadIdx.x;
    if (k < 512) {
        float s = 0.f;
        for (int c = 0; c < 64; c++) {
            float v = emb[k * 64 + c];
            s = __fadd_rn(s, __fmul_rn(v, v));
            g_embT[c * 512 + k] = v;
        }
        g_en[k] = s;
    }
}

// ------------------------- e1: 1->32, k4 s2 p1, relu -----------------------
__global__ __launch_bounds__(128) void k_e1(const float* __restrict__ x,
                                            const float* __restrict__ w,
                                            const float* __restrict__ b) {
    __shared__ float s_in[4 * 258];
    __shared__ float s_w[512];
    const int oh = blockIdx.x, n = blockIdx.y, t = threadIdx.x;
    const int lane = t & 31, wrp = t >> 5;
    {
        int r = wrp;
        int ih = 2 * oh - 1 + r;
        bool rowok = (ih >= 0 && ih < 256);
        const float* src = x + n * 65536 + ih * 256;
        float* dst = s_in + r * 258;
#pragma unroll
        for (int k = 0; k < 9; k++) {
            int c = lane + 32 * k;
            if (c < 258) {
                int iw = c - 1;
                dst[c] = (rowok && iw >= 0 && iw < 256) ? src[iw] : 0.f;
            }
        }
    }
    for (int i = t; i < 512; i += 128) s_w[i] = w[i];
    __syncthreads();
    float acc[32];
#pragma unroll
    for (int o = 0; o < 32; o++) acc[o] = 0.f;
    const int ow = t;
#pragma unroll
    for (int k = 0; k < 16; k++) {
        float v = s_in[(k >> 2) * 258 + 2 * ow + (k & 3)];
#pragma unroll
        for (int o = 0; o < 32; o++) acc[o] = fmaf(v, s_w[o * 16 + k], acc[o]);
    }
    for (int o = 0; o < 32; o++) {
        float r = __fadd_rn(acc[o], b[o]);
        g_h1[((n * 32 + o) * 128 + oh) * 128 + ow] = r > 0.f ? r : 0.f;
    }
}

// ------------------------- e2: 32->64, k4 s2 p1, relu ----------------------
// Block: 2 oh x 64 ow x 64 oc. Thread: tow(16) x tog(8) x toh(2);
// ow = tow + 16*i (conflict-free LDS), oc = tog*8..+7 (4 f32x2 pairs).
// Chain: kh, kw outer; ic 0..31 innermost (Eigen).
__global__ __launch_bounds__(256) void k_e2(const float* __restrict__ w,
                                            const float* __restrict__ b) {
    extern __shared__ float sm[];
    float* s_in = sm;            // [r(6)][ic(32)][130] = 24960
    float* s_w  = sm + 24960;    // per (kh,kw): [ic(32)][oc(64)] = 2048
    const int oh0 = blockIdx.x * 2, n = blockIdx.y, t = threadIdx.x;
    const int tow = t & 15, tog = (t >> 4) & 7, toh = t >> 7;
    const int lane = t & 31, wrp = t >> 5;
#pragma unroll 1
    for (int m = 0; m < 24; m++) {           // 192 rows = [r6][ic32]
        int row = wrp * 24 + m;
        int r = row >> 5, ic = row & 31;
        int ih = 2 * oh0 - 1 + r;
        bool rowok = (ih >= 0 && ih < 128);
        const float* src = g_h1 + ((n * 32 + ic) * 128 + ih) * 128;
        float* dst = s_in + row * 130;
#pragma unroll
        for (int k = 0; k < 5; k++) {
            int c = lane + 32 * k;
            if (c < 130) {
                int iw = c - 1;
                dst[c] = (rowok && iw >= 0 && iw < 128) ? src[iw] : 0.f;
            }
        }
    }
    u64 acc[4][4];
#pragma unroll
    for (int i = 0; i < 4; i++)
#pragma unroll
        for (int j = 0; j < 4; j++) acc[i][j] = 0ull;
#pragma unroll 1
    for (int kh = 0; kh < 4; kh++) {
#pragma unroll 1
        for (int kw = 0; kw < 4; kw++) {
            __syncthreads();
            for (int i = t; i < 2048; i += 256) {
                int ic = i >> 6, oc = i & 63;
                s_w[i] = w[((oc * 32 + ic) << 4) + (kh << 2) + kw];
            }
            __syncthreads();
            const float* pin = s_in + (2 * toh + kh) * 4160 + 2 * tow + kw;
            const float* pwb = s_w + (tog << 3);
#pragma unroll 4
            for (int ic = 0; ic < 32; ic++) {
                const float* pw = pwb + (ic << 6);
                ulonglong2 wa = *(const ulonglong2*)(pw);
                ulonglong2 wb = *(const ulonglong2*)(pw + 4);
                const float* q = pin + ic * 130;
#pragma unroll
                for (int i = 0; i < 4; i++) {
                    float v = q[32 * i];
                    u64 vv = pk2(v, v);
                    acc[i][0] = f2fma(vv, wa.x, acc[i][0]);
                    acc[i][1] = f2fma(vv, wa.y, acc[i][1]);
                    acc[i][2] = f2fma(vv, wb.x, acc[i][2]);
                    acc[i][3] = f2fma(vv, wb.y, acc[i][3]);
                }
            }
        }
    }
    const int oh = oh0 + toh;
#pragma unroll
    for (int i = 0; i < 4; i++) {
        int ow = tow + 16 * i;
#pragma unroll
        for (int j = 0; j < 4; j++) {
            float2 f = upk(acc[i][j]);
            int oc0 = tog * 8 + 2 * j;
            float r0 = __fadd_rn(f.x, b[oc0]);
            float r1 = __fadd_rn(f.y, b[oc0 + 1]);
            g_h2[((n * 64 + oc0) * 64 + oh) * 64 + ow]     = r0 > 0.f ? r0 : 0.f;
            g_h2[((n * 64 + oc0 + 1) * 64 + oh) * 64 + ow] = r1 > 0.f ? r1 : 0.f;
        }
    }
}

// ------------------------- e3: 64->64, k3 s1 p1, relu ----------------------
// Block: 2 oh x 64 ow x 64 oc. Thread: tow(16) x tog(8) x toh(2).
__global__ __launch_bounds__(256) void k_e3(const float* __restrict__ w,
                                            const float* __restrict__ b,
                                            float* __restrict__ ze) {
    extern __shared__ float sm[];
    float* s_in = sm;            // [r(4)][ic(64)][66] = 16896
    float* s_w  = sm + 16896;    // per (kh,kw): [ic(64)][oc(64)] = 4096
    const int oh0 = blockIdx.x * 2, n = blockIdx.y, t = threadIdx.x;
    const int tow = t & 15, tog = (t >> 4) & 7, toh = t >> 7;
    const int lane = t & 31, wrp = t >> 5;
#pragma unroll 1
    for (int m = 0; m < 32; m++) {           // 256 rows = [r4][ic64]
        int row = wrp * 32 + m;
        int r = row >> 6, ic = row & 63;
        int ih = oh0 - 1 + r;
        bool rowok = (ih >= 0 && ih < 64);
        const float* src = g_h2 + ((n * 64 + ic) * 64 + ih) * 64;
        float* dst = s_in + row * 66;
#pragma unroll
        for (int k = 0; k < 3; k++) {
            int c = lane + 32 * k;
            if (c < 66) {
                int iw = c - 1;
                dst[c] = (rowok && iw >= 0 && iw < 64) ? src[iw] : 0.f;
            }
        }
    }
    u64 acc[4][4];
#pragma unroll
    for (int i = 0; i < 4; i++)
#pragma unroll
        for (int j = 0; j < 4; j++) acc[i][j] = 0ull;
#pragma unroll 1
    for (int kh = 0; kh < 3; kh++) {
#pragma unroll 1
        for (int kw = 0; kw < 3; kw++) {
            __syncthreads();
            for (int i = t; i < 4096; i += 256) {
                int ic = i >> 6, oc = i & 63;
                s_w[i] = w[(oc * 64 + ic) * 9 + kh * 3 + kw];
            }
            __syncthreads();
            const float* pin = s_in + (toh + kh) * 4224 + tow + kw;
            const float* pwb = s_w + (tog << 3);
#pragma unroll 4
            for (int ic = 0; ic < 64; ic++) {
                const float* pw = pwb + (ic << 6);
                ulonglong2 wa = *(const ulonglong2*)(pw);
                ulonglong2 wb = *(const ulonglong2*)(pw + 4);
                const float* q = pin + ic * 66;
#pragma unroll
                for (int i = 0; i < 4; i++) {
                    float v = q[16 * i];
                    u64 vv = pk2(v, v);
                    acc[i][0] = f2fma(vv, wa.x, acc[i][0]);
                    acc[i][1] = f2fma(vv, wa.y, acc[i][1]);
                    acc[i][2] = f2fma(vv, wb.x, acc[i][2]);
                    acc[i][3] = f2fma(vv, wb.y, acc[i][3]);
                }
            }
        }
    }
    const int oh = oh0 + toh;
#pragma unroll
    for (int i = 0; i < 4; i++) {
        int ow = tow + 16 * i;
#pragma unroll
        for (int j = 0; j < 4; j++) {
            float2 f = upk(acc[i][j]);
            int oc0 = tog * 8 + 2 * j;
            float r0 = __fadd_rn(f.x, b[oc0]);
            float r1 = __fadd_rn(f.y, b[oc0 + 1]);
            ze[((n * 64 + oc0) * 64 + oh) * 64 + ow]     = r0 > 0.f ? r0 : 0.f;
            ze[((n * 64 + oc0 + 1) * 64 + oh) * 64 + ow] = r1 > 0.f ? r1 : 0.f;
        }
    }
}

// ------------------------- VQ argmin + gather ------------------------------
__global__ __launch_bounds__(256) void k_vq(const float* __restrict__ ze,
                                            const float* __restrict__ emb,
                                            float* __restrict__ zq) {
    __shared__ __align__(16) float s_z[4096];   // [c(64)][pos(64)]
    __shared__ __align__(16) float s_e[4096];   // [c(64)][code_local(64)]
    __shared__ float s_zz[64];
    __shared__ float s_en[512];
    __shared__ float s_bv[256];
    __shared__ int s_bi[256];
    __shared__ int s_idx[64];
    const int h = blockIdx.x, n = blockIdx.y, t = threadIdx.x;
    const int pos = t & 63, kg = t >> 6;
    for (int i = t; i < 4096; i += 256)
        s_z[i] = ze[(n * 64 + (i >> 6)) * 4096 + h * 64 + (i & 63)];
    for (int i = t; i < 512; i += 256) s_en[i] = g_en[i];
    __syncthreads();
    if (t < 64) {
        float a = 0.f;
        for (int c = 0; c < 64; c++) {
            float v = s_z[c * 64 + t];
            a = __fadd_rn(a, __fmul_rn(v, v));
        }
        s_zz[t] = a;
    }
    float bv = 3.4e38f;
    int bi = 0;
    for (int ch = 0; ch < 8; ch++) {
        __syncthreads();
        for (int i = t; i < 4096; i += 256)
            s_e[i] = g_embT[(i >> 6) * 512 + ch * 64 + (i & 63)];
        __syncthreads();
        const float zz = s_zz[pos];
        u64 dot[8];
#pragma unroll
        for (int j = 0; j < 8; j++) dot[j] = 0ull;
#pragma unroll 4
        for (int c = 0; c < 64; c++) {
            float v = s_z[c * 64 + pos];
            u64 vv = pk2(v, v);
            const ulonglong2* pe = (const ulonglong2*)(s_e + c * 64 + kg * 16);
#pragma unroll
            for (int j = 0; j < 4; j++) {
                ulonglong2 e2v = pe[j];
                dot[2 * j]     = f2fma(vv, e2v.x, dot[2 * j]);
                dot[2 * j + 1] = f2fma(vv, e2v.y, dot[2 * j + 1]);
            }
        }
#pragma unroll
        for (int j = 0; j < 8; j++) {
            float2 f = upk(dot[j]);
            int code0 = ch * 64 + kg * 16 + 2 * j;
            float d0 = __fadd_rn(__fsub_rn(zz, __fmul_rn(2.0f, f.x)), s_en[code0]);
            float d1 = __fadd_rn(__fsub_rn(zz, __fmul_rn(2.0f, f.y)), s_en[code0 + 1]);
            if (d0 < bv) { bv = d0; bi = code0; }
            if (d1 < bv) { bv = d1; bi = code0 + 1; }
        }
    }
    s_bv[t] = bv;
    s_bi[t] = bi;
    __syncthreads();
    if (t < 64) {
        for (int q = 1; q < 4; q++) {
            float v2 = s_bv[t + q * 64];
            int i2 = s_bi[t + q * 64];
            if (v2 < bv || (v2 == bv && i2 < bi)) { bv = v2; bi = i2; }
        }
        s_idx[t] = bi;
    }
    __syncthreads();
    for (int i = t; i < 4096; i += 256) {
        int c = i >> 6, wq = i & 63;
        zq[(n * 64 + c) * 4096 + h * 64 + wq] = emb[s_idx[wq] * 64 + c];
    }
}

// --------------- d1: convT 64->32, k3 s1 p1, relu; in = ze+(zq-ze) ---------
// Block: 4 oh x 64 ow x 32 oc. Thread: tow(16) x tog(4) x toh(4).
__global__ __launch_bounds__(256) void k_d1(const float* __restrict__ ze,
                                            const float* __restrict__ zq,
                                            const float* __restrict__ w,
                                            const float* __restrict__ b) {
    extern __shared__ float sm[];
    float* s_in = sm;            // [r(6)][ic(64)][66] = 25344
    float* s_w  = sm + 25344;    // per (kh,kw): [ic(64)][oc(32)] = 2048
    const int oh0 = blockIdx.x * 4, n = blockIdx.y, t = threadIdx.x;
    const int tow = t & 15, tog = (t >> 4) & 3, toh = t >> 6;
    const int lane = t & 31, wrp = t >> 5;
#pragma unroll 1
    for (int m = 0; m < 48; m++) {           // 384 rows = [r6][ic64]
        int row = wrp * 48 + m;
        int r = row >> 6, ic = row & 63;
        int ih = oh0 - 1 + r;
        bool rowok = (ih >= 0 && ih < 64);
        const float* pz = ze + ((n * 64 + ic) * 64 + ih) * 64;
        const float* pq = zq + ((n * 64 + ic) * 64 + ih) * 64;
        float* dst = s_in + row * 66;
#pragma unroll
        for (int k = 0; k < 3; k++) {
            int c = lane + 32 * k;
            if (c < 66) {
                int iw = c - 1;
                float v = 0.f;
                if (rowok && iw >= 0 && iw < 64) {
                    float a = pz[iw], q = pq[iw];
                    v = __fadd_rn(a, __fsub_rn(q, a));
                }
                dst[c] = v;
            }
        }
    }
    u64 acc[4][4];
#pragma unroll
    for (int i = 0; i < 4; i++)
#pragma unroll
        for (int j = 0; j < 4; j++) acc[i][j] = 0ull;
#pragma unroll 1
    for (int kh = 0; kh < 3; kh++) {
#pragma unroll 1
        for (int kw = 0; kw < 3; kw++) {
            __syncthreads();
            for (int i = t; i < 2048; i += 256) {
                int ic = i >> 5, oc = i & 31;
                s_w[i] = w[(ic * 32 + oc) * 9 + 8 - kh * 3 - kw];
            }
            __syncthreads();
            const float* pin = s_in + (toh + kh) * 4224 + tow + kw;
            const float* pwb = s_w + (tog << 3);
#pragma unroll 4
            for (int ic = 0; ic < 64; ic++) {
                const float* pw = pwb + (ic << 5);
                ulonglong2 wa = *(const ulonglong2*)(pw);
                ulonglong2 wb = *(const ulonglong2*)(pw + 4);
                const float* q = pin + ic * 66;
#pragma unroll
                for (int i = 0; i < 4; i++) {
                    float v = q[16 * i];
                    u64 vv = pk2(v, v);
                    acc[i][0] = f2fma(vv, wa.x, acc[i][0]);
                    acc[i][1] = f2fma(vv, wa.y, acc[i][1]);
                    acc[i][2] = f2fma(vv, wb.x, acc[i][2]);
                    acc[i][3] = f2fma(vv, wb.y, acc[i][3]);
                }
            }
        }
    }
    const int oh = oh0 + toh;
#pragma unroll
    for (int i = 0; i < 4; i++) {
        int ow = tow + 16 * i;
#pragma unroll
        for (int j = 0; j < 4; j++) {
            float2 f = upk(acc[i][j]);
            int oc0 = tog * 8 + 2 * j;
            float r0 = f.x + b[oc0];
            float r1 = f.y + b[oc0 + 1];
            g_d1o[((n * 32 + oc0) * 64 + oh) * 64 + ow]     = r0 > 0.f ? r0 : 0.f;
            g_d1o[((n * 32 + oc0 + 1) * 64 + oh) * 64 + ow] = r1 > 0.f ? r1 : 0.f;
        }
    }
}

// --------------- d2: convT 32->64, k4 s2 p1, relu (parity-decomposed) ------
// ow = 2*(u + 16*i) + p : conflict-free input LDS.
__global__ __launch_bounds__(256) void k_d2(const float* __restrict__ w,
                                            const float* __restrict__ b) {
    __shared__ __align__(16) float s_in[2112];   // [r(2)][ic(16)][66]
    __shared__ __align__(16) float s_w[8192];    // [ic(16)][r(2)][kw(4)][oc(64)]
    const int oh = blockIdx.x, n = blockIdx.y, t = threadIdx.x;
    const int p = t & 1, u = (t >> 1) & 15, tog = t >> 5;
    const int lane = t & 31, wrp = t >> 5;
    const int kh_a = 1 - (oh & 1);
    const int ih_a = (oh + 1 - kh_a) >> 1;
    const int kw_a = 1 - p;
    u64 acc[4][4];
#pragma unroll
    for (int i = 0; i < 4; i++)
#pragma unroll
        for (int j = 0; j < 4; j++) acc[i][j] = 0ull;
#pragma unroll 1
    for (int cc = 0; cc < 2; cc++) {
        __syncthreads();
#pragma unroll
        for (int m = 0; m < 4; m++) {
            int row = wrp * 4 + m;
            int r = row >> 4, ic = row & 15;
            int ih = (r == 0) ? ih_a : ih_a - 1;
            bool rowok = (ih >= 0 && ih < 64);
            const float* src = g_d1o + ((n * 32 + cc * 16 + ic) * 64 + ih) * 64;
            float* dst = s_in + row * 66;
#pragma unroll
            for (int k = 0; k < 3; k++) {
                int c = lane + 32 * k;
                if (c < 66) {
                    int iw = c - 1;
                    dst[c] = (rowok && iw >= 0 && iw < 64) ? src[iw] : 0.f;
                }
            }
        }
        for (int i = t; i < 8192; i += 256) {
            int ic = i >> 9, rem = i & 511;
            int r = rem >> 8, kw = (rem >> 6) & 3, oc = rem & 63;
            s_w[i] = w[(((cc * 16 + ic) * 64 + oc) << 4) + (kh_a + 2 * r) * 4 + kw];
        }
        __syncthreads();
#pragma unroll 2
        for (int ic = 0; ic < 16; ic++) {
#pragma unroll
            for (int r = 0; r < 2; r++) {
#pragma unroll
                for (int m = 0; m < 2; m++) {
                    int kw = kw_a + 2 * m;
                    const ulonglong2* pw = (const ulonglong2*)(s_w + ((ic * 2 + r) * 4 + kw) * 64 + tog * 8);
                    const float* q = s_in + r * 1056 + ic * 66 + u + p - m + 1;
                    ulonglong2 w01 = pw[0], w23 = pw[1];
#pragma unroll
                    for (int i = 0; i < 4; i++) {
                        float v = q[16 * i];
                        u64 vv = pk2(v, v);
                        acc[i][0] = f2fma(vv, w01.x, acc[i][0]);
                        acc[i][1] = f2fma(vv, w01.y, acc[i][1]);
                        acc[i][2] = f2fma(vv, w23.x, acc[i][2]);
                        acc[i][3] = f2fma(vv, w23.y, acc[i][3]);
                    }
                }
            }
        }
    }
#pragma unroll
    for (int i = 0; i < 4; i++) {
        int ow = 2 * (u + 16 * i) + p;
#pragma unroll
        for (int j = 0; j < 4; j++) {
            float2 f = upk(acc[i][j]);
            int oc0 = tog * 8 + 2 * j;
            float r0 = f.x + b[oc0];
            float r1 = f.y + b[oc0 + 1];
            g_d2o[((n * 64 + oc0) * 128 + oh) * 128 + ow]     = r0 > 0.f ? r0 : 0.f;
            g_d2o[((n * 64 + oc0 + 1) * 128 + oh) * 128 + ow] = r1 > 0.f ? r1 : 0.f;
        }
    }
}

// --------------- d3: convT 64->1, k4 s2 p1 (no relu) -----------------------
__global__ __launch_bounds__(256) void k_d3(const float* __restrict__ w,
                                            const float* __restrict__ bb,
                                            float* __restrict__ xh) {
    __shared__ float s_in[8320];   // [r(2)][ic(32)][130]
    __shared__ float s_w[512];
    const int oh = blockIdx.x, n = blockIdx.y, t = threadIdx.x;
    const int ow = t;
    const int lane = t & 31, wrp = t >> 5;
    const int kh_a = 1 - (oh & 1);
    const int ih_a = (oh + 1 - kh_a) >> 1;
    const int ih_b = ih_a - 1;
    const int kw_a = 1 - (ow & 1);
    const int iw_a = (ow + 1 - kw_a) >> 1;
    for (int i = t; i < 512; i += 256) {
        int ic = i >> 3, r = (i >> 2) & 1, kw = i & 3;
        int kh = kh_a + 2 * r;
        s_w[i] = w[ic * 16 + kh * 4 + kw];
    }
    float acc = 0.f;
#pragma unroll 1
    for (int cc = 0; cc < 2; cc++) {
        __syncthreads();
#pragma unroll
        for (int m = 0; m < 8; m++) {
            int row = wrp * 8 + m;
            int r = row >> 5, ic = row & 31;
            int ih = (r == 0) ? ih_a : ih_b;
            bool rowok = (ih >= 0 && ih < 128);
            const float* src = g_d2o + ((n * 64 + cc * 32 + ic) * 128 + ih) * 128;
            float* dst = s_in + row * 130;
#pragma unroll
            for (int k = 0; k < 5; k++) {
                int c = lane + 32 * k;
                if (c < 130) {
                    int iw = c - 1;
                    dst[c] = (rowok && iw >= 0 && iw < 128) ? src[iw] : 0.f;
                }
            }
        }
        __syncthreads();
#pragma unroll 4
        for (int ic = 0; ic < 32; ic++) {
#pragma unroll
            for (int r = 0; r < 2; r++) {
#pragma unroll
                for (int m = 0; m < 2; m++) {
                    float v = s_in[r * 4160 + ic * 130 + iw_a - m + 1];
                    acc = fmaf(v, s_w[((cc * 32 + ic) << 3) + r * 4 + kw_a + 2 * m], acc);
                }
            }
        }
    }
    xh[n * 65536 + oh * 256 + ow] = __fadd_rn(acc, bb[0]);
}

// ---------------------------------------------------------------------------
extern "C" void kernel_launch(void* const* d_in, const int* in_sizes, int n_in,
                              void* d_out, int out_size) {
    const float* x   = (const float*)d_in[0];
    const float* e1w = (const float*)d_in[1];
    const float* e1b = (const float*)d_in[2];
    const float* e2w = (const float*)d_in[3];
    const float* e2b = (const float*)d_in[4];
    const float* e3w = (const float*)d_in[5];
    const float* e3b = (const float*)d_in[6];
    const float* emb = (const float*)d_in[7];
    const float* d1w = (const float*)d_in[8];
    const float* d1b = (const float*)d_in[9];
    const float* d2w = (const float*)d_in[10];
    const float* d2b = (const float*)d_in[11];
    const float* d3w = (const float*)d_in[12];
    const float* d3b = (const float*)d_in[13];

    float* out = (float*)d_out;
    float* xh = out;
    float* ze = out + 4194304;
    float* zq = out + 4194304 + 16777216;

    static bool attr_done = false;
    if (!attr_done) {
        cudaFuncSetAttribute(k_e2, cudaFuncAttributeMaxDynamicSharedMemorySize, 108032);
        cudaFuncSetAttribute(k_e3, cudaFuncAttributeMaxDynamicSharedMemorySize, 83968);
        cudaFuncSetAttribute(k_d1, cudaFuncAttributeMaxDynamicSharedMemorySize, 109568);
        attr_done = true;
    }

    k_en<<<2, 256>>>(emb);
    k_e1<<<dim3(128, 64), 128>>>(x, e1w, e1b);
    k_e2<<<dim3(32, 64), 256, 108032>>>(e2w, e2b);
    k_e3<<<dim3(32, 64), 256, 83968>>>(e3w, e3b, ze);
    k_vq<<<dim3(64, 64), 256>>>(ze, emb, zq);
    k_d1<<<dim3(16, 64), 256, 109568>>>(ze, zq, d1w, d1b);
    k_d2<<<dim3(128, 64), 256>>>(d2w, d2b);
    k_d3<<<dim3(256, 64), 256>>>(d3w, d3b, xh);
}